// round 10
// baseline (speedup 1.0000x reference)
#include <cuda_runtime.h>
#include <cuda_fp16.h>
#include <math.h>
#include <stdint.h>

#define D_MODEL 1024
#define D_FF    4096
#define N_EXP   8
#define MAX_N   4096
#define MAX_PAIRS (2*MAX_N)

// ---- scratch (static device globals; no runtime allocation) ----
__device__ __half g_xh[(size_t)MAX_N * D_MODEL];           // x in half
__device__ __half g_W1t[(size_t)N_EXP * D_FF * D_MODEL];   // W1^T: [e][n=4096][k=1024] half
__device__ __half g_W2t[(size_t)N_EXP * D_MODEL * D_FF];   // W2^T: [e][n=1024][k=4096] half
__device__ __half g_Hh[(size_t)MAX_PAIRS * D_FF];          // gelu(x@W1) per pair, half
__device__ float  g_pairout[(size_t)MAX_PAIRS * D_MODEL];  // per-pair weighted FFN out
__device__ int    g_pairlist[MAX_PAIRS];
__device__ int    g_cnt[N_EXP];
__device__ int    g_off[N_EXP];
__device__ int    g_tokexp[MAX_PAIRS];
__device__ float  g_tokw[MAX_PAIRS];

__device__ __forceinline__ float gelu_exact(float v) {
    return 0.5f * v * (1.0f + erff(v * 0.70710678118654752440f));
}
__device__ __forceinline__ uint32_t smem_u32(const void* p) {
    uint32_t a;
    asm("{ .reg .u64 t; cvta.to.shared.u64 t, %1; cvt.u32.u64 %0, t; }" : "=r"(a) : "l"(p));
    return a;
}
__device__ __forceinline__ void cp_async16(uint32_t dst, const void* src, int srcsize) {
    asm volatile("cp.async.ca.shared.global [%0], [%1], 16, %2;"
                 :: "r"(dst), "l"(src), "r"(srcsize) : "memory");
}
__device__ __forceinline__ void cp_commit() { asm volatile("cp.async.commit_group;" ::: "memory"); }
__device__ __forceinline__ void cp_wait1()  { asm volatile("cp.async.wait_group 1;" ::: "memory"); }

__device__ __forceinline__ void ldsm_x4(uint32_t* r, uint32_t addr) {
    asm volatile("ldmatrix.sync.aligned.m8n8.x4.shared.b16 {%0,%1,%2,%3}, [%4];"
                 : "=r"(r[0]), "=r"(r[1]), "=r"(r[2]), "=r"(r[3]) : "r"(addr));
}
__device__ __forceinline__ void mma_f16(float* d, const uint32_t* a, const uint32_t* b) {
    asm volatile(
        "mma.sync.aligned.m16n8k16.row.col.f32.f16.f16.f32 "
        "{%0,%1,%2,%3}, {%4,%5,%6,%7}, {%8,%9}, {%0,%1,%2,%3};"
        : "+f"(d[0]), "+f"(d[1]), "+f"(d[2]), "+f"(d[3])
        : "r"(a[0]), "r"(a[1]), "r"(a[2]), "r"(a[3]), "r"(b[0]), "r"(b[1]));
}

// ---------------- gate: logits -> softmax -> top2 (float4 loads) ----------------
__global__ void gate_kernel(const float* __restrict__ x,
                            const float* __restrict__ gw, int N) {
    __shared__ float s_gw[N_EXP][D_MODEL];
    int tid = threadIdx.x;
    for (int i = tid; i < N_EXP * D_MODEL / 4; i += blockDim.x) {
        float4 v = ((const float4*)gw)[i];
        int e = i >> 8, c = (i & 255) * 4;
        s_gw[e][c] = v.x; s_gw[e][c + 1] = v.y; s_gw[e][c + 2] = v.z; s_gw[e][c + 3] = v.w;
    }
    __syncthreads();

    int warp = tid >> 5, lane = tid & 31;
    int t = blockIdx.x * 8 + warp;
    if (t >= N) return;

    const float4* xr = (const float4*)(x + (size_t)t * D_MODEL);
    float acc[N_EXP];
#pragma unroll
    for (int e = 0; e < N_EXP; e++) acc[e] = 0.f;
#pragma unroll
    for (int it = 0; it < D_MODEL / 128; it++) {
        int d4 = it * 32 + lane;
        float4 xv = xr[d4];
        int d = d4 * 4;
#pragma unroll
        for (int e = 0; e < N_EXP; e++) {
            acc[e] += xv.x * s_gw[e][d] + xv.y * s_gw[e][d + 1]
                    + xv.z * s_gw[e][d + 2] + xv.w * s_gw[e][d + 3];
        }
    }
#pragma unroll
    for (int e = 0; e < N_EXP; e++) {
#pragma unroll
        for (int o = 16; o > 0; o >>= 1)
            acc[e] += __shfl_xor_sync(0xffffffffu, acc[e], o);
    }
    if (lane == 0) {
        float mx = acc[0];
#pragma unroll
        for (int e = 1; e < N_EXP; e++) mx = fmaxf(mx, acc[e]);
        float p[N_EXP]; float sum = 0.f;
#pragma unroll
        for (int e = 0; e < N_EXP; e++) { p[e] = expf(acc[e] - mx); sum += p[e]; }
        float inv = 1.0f / sum;
#pragma unroll
        for (int e = 0; e < N_EXP; e++) p[e] *= inv;
        int e0 = 0;
#pragma unroll
        for (int e = 1; e < N_EXP; e++) if (p[e] > p[e0]) e0 = e;
        int e1 = (e0 == 0) ? 1 : 0;
#pragma unroll
        for (int e = 0; e < N_EXP; e++) if (e != e0 && p[e] > p[e1]) e1 = e;
        g_tokexp[2 * t + 0] = e0; g_tokw[2 * t + 0] = p[e0];
        g_tokexp[2 * t + 1] = e1; g_tokw[2 * t + 1] = p[e1];
    }
}

// ------- deterministic per-expert compaction (stable counting sort) -------
__global__ void build_kernel(int N) {
    __shared__ int s_cnt[N_EXP];
    int tid = threadIdx.x, warp = tid >> 5, lane = tid & 31;
    int total = 2 * N;
    if (warp < N_EXP) {
        int c = 0;
        for (int i = lane; i < total; i += 32) c += (g_tokexp[i] == warp);
#pragma unroll
        for (int o = 16; o > 0; o >>= 1) c += __shfl_xor_sync(0xffffffffu, c, o);
        if (lane == 0) s_cnt[warp] = c;
    }
    __syncthreads();
    if (tid == 0) {
        int o = 0;
        for (int e = 0; e < N_EXP; e++) { g_off[e] = o; g_cnt[e] = s_cnt[e]; o += s_cnt[e]; }
    }
    __syncthreads();
    if (warp < N_EXP) {
        int run = g_off[warp];
        for (int base = 0; base < total; base += 32) {
            int i = base + lane;
            bool m = (i < total) && (g_tokexp[i] == warp);
            unsigned b = __ballot_sync(0xffffffffu, m);
            if (m) g_pairlist[run + __popc(b & ((1u << lane) - 1u))] = i;
            run += __popc(b);
        }
    }
}

// ---------------- prepass: convert & transpose ----------------
__global__ void convert_x_kernel(const float* __restrict__ x, int total4) {
    int i = blockIdx.x * blockDim.x + threadIdx.x;
    if (i >= total4) return;
    float4 v = ((const float4*)x)[i];
    __half2* o = (__half2*)g_xh;
    o[2 * i + 0] = __floats2half2_rn(v.x, v.y);
    o[2 * i + 1] = __floats2half2_rn(v.z, v.w);
}

// src [E][K][Nn] f32 -> dst [E][Nn][K] half  (tiled transpose, 8B coalesced writes)
__global__ void transpose_kernel(const float* __restrict__ src, __half* __restrict__ dst,
                                 int K, int Nn) {
    __shared__ float tile[32][33];
    int e = blockIdx.z;
    const float* s = src + (size_t)e * K * Nn;
    __half* d = dst + (size_t)e * K * Nn;
    int n0 = blockIdx.x * 32, k0 = blockIdx.y * 32;
    int tx = threadIdx.x, ty = threadIdx.y;  // 32 x 8
#pragma unroll
    for (int r = 0; r < 32; r += 8)
        tile[ty + r][tx] = s[(size_t)(k0 + ty + r) * Nn + n0 + tx];
    __syncthreads();
    int tid = ty * 32 + tx;
    int row = tid >> 3, ch = tid & 7;
    float v0 = tile[ch * 4 + 0][row];
    float v1 = tile[ch * 4 + 1][row];
    float v2 = tile[ch * 4 + 2][row];
    float v3 = tile[ch * 4 + 3][row];
    __half2 h0 = __floats2half2_rn(v0, v1);
    __half2 h1 = __floats2half2_rn(v2, v3);
    uint2 pack = make_uint2(*(uint32_t*)&h0, *(uint32_t*)&h1);
    *(uint2*)(d + (size_t)(n0 + row) * K + k0 + ch * 4) = pack;
}

// =================== fp16 mma GEMM: cp.async + ldmatrix, 2-stage ===================
#define PITCH 144
#define A_STAGE_BYTES (128 * PITCH)
#define STAGE_BYTES   (2 * 128 * PITCH)
#define N_STAGES 2
#define SMEM_TOT (2048 + N_STAGES * STAGE_BYTES)

template <int MODE>
__global__ void __launch_bounds__(256, 2) moe_gemm(const __half* __restrict__ Wt, int e) {
    constexpr int Ktot = (MODE == 0) ? D_MODEL : D_FF;
    constexpr int ITERS = Ktot / 64;

    int cnt = g_cnt[e];
    int row0 = blockIdx.y * 128;
    if (row0 >= cnt) return;
    int off = g_off[e];
    int fn0 = blockIdx.x * 128;
    const __half* We = Wt + (size_t)e * Ktot * ((MODE == 0) ? D_FF : D_MODEL);

    extern __shared__ __align__(128) char smem[];
    const __half** s_aptr = (const __half**)smem;
    int* s_pair = (int*)(smem + 1024);
    uint32_t sb = smem_u32(smem);
    uint32_t stage_base = sb + 2048;

    int tid = threadIdx.x, wid = tid >> 5, lane = tid & 31;

    if (tid < 128) {
        int r = row0 + tid;
        const __half* ip = nullptr; int p = -1;
        if (r < cnt) {
            p = g_pairlist[off + r];
            ip = (MODE == 0) ? (g_xh + (size_t)(p >> 1) * D_MODEL)
                             : (g_Hh + (size_t)p * D_FF);
        }
        s_aptr[tid] = ip; s_pair[tid] = p;
    }
    __syncthreads();

    int srow = tid >> 1;
    int halfsel = tid & 1;
    const __half* arow = s_aptr[srow];
    int a_sz = arow ? 16 : 0;
    if (!arow) arow = g_xh;
    const __half* brow = We + (size_t)(fn0 + srow) * Ktot;

    auto stage = [&](int it) {
        if (it < ITERS) {
            uint32_t sA = stage_base + (it % N_STAGES) * STAGE_BYTES + srow * PITCH + halfsel * 64;
            uint32_t sB = sA + A_STAGE_BYTES;
            const char* ga = (const char*)(arow + it * 64) + halfsel * 64;
            const char* gb = (const char*)(brow + it * 64) + halfsel * 64;
#pragma unroll
            for (int c = 0; c < 4; c++) cp_async16(sA + c * 16, ga + c * 16, a_sz);
#pragma unroll
            for (int c = 0; c < 4; c++) cp_async16(sB + c * 16, gb + c * 16, 16);
        }
        cp_commit();
    };

    float d[4][4][4];
#pragma unroll
    for (int i = 0; i < 4; i++)
#pragma unroll
        for (int j = 0; j < 4; j++)
#pragma unroll
            for (int r = 0; r < 4; r++) d[i][j][r] = 0.f;

    int wm = wid >> 2, wn = wid & 3;  // warp tile: rows wm*64.., cols wn*32..

    int a_row_l = (lane & 15);
    int a_koff  = (lane >> 4) * 16;
    int b_grp   = lane >> 3;
    int b_row_l = (b_grp >> 1) * 8 + (lane & 7);
    int b_koff  = (b_grp & 1) * 16;

    stage(0);
    stage(1);

    for (int it = 0; it < ITERS; ++it) {
        cp_wait1();
        __syncthreads();
        uint32_t A = stage_base + (it % N_STAGES) * STAGE_BYTES;
        uint32_t B = A + A_STAGE_BYTES;
#pragma unroll
        for (int ks = 0; ks < 4; ks++) {
            uint32_t a[4][4], b[2][4];
#pragma unroll
            for (int i = 0; i < 4; i++)
                ldsm_x4(a[i], A + (wm * 64 + i * 16 + a_row_l) * PITCH + ks * 32 + a_koff);
#pragma unroll
            for (int jj = 0; jj < 2; jj++)
                ldsm_x4(b[jj], B + (wn * 32 + jj * 16 + b_row_l) * PITCH + ks * 32 + b_koff);
#pragma unroll
            for (int i = 0; i < 4; i++)
#pragma unroll
                for (int j = 0; j < 4; j++)
                    mma_f16(d[i][j], a[i], &b[j >> 1][(j & 1) * 2]);
        }
        __syncthreads();
        stage(it + 2);
    }

    // ---- epilogue from accumulators (direct stores) ----
    int g = lane >> 2, t4 = lane & 3;
#pragma unroll
    for (int i = 0; i < 4; i++) {
        int rl = wm * 64 + i * 16 + g;
        int pL = s_pair[rl], pH = s_pair[rl + 8];
#pragma unroll
        for (int j = 0; j < 4; j++) {
            int c = wn * 32 + j * 8 + t4 * 2;
            if (MODE == 0) {
                if (pL >= 0) {
                    __half2* o = (__half2*)(g_Hh + (size_t)pL * D_FF + fn0 + c);
                    *o = __floats2half2_rn(gelu_exact(d[i][j][0]), gelu_exact(d[i][j][1]));
                }
                if (pH >= 0) {
                    __half2* o = (__half2*)(g_Hh + (size_t)pH * D_FF + fn0 + c);
                    *o = __floats2half2_rn(gelu_exact(d[i][j][2]), gelu_exact(d[i][j][3]));
                }
            } else {
                if (pL >= 0) {
                    float w = g_tokw[pL];
                    *(float2*)(g_pairout + (size_t)pL * D_MODEL + fn0 + c) =
                        make_float2(w * d[i][j][0], w * d[i][j][1]);
                }
                if (pH >= 0) {
                    float w = g_tokw[pH];
                    *(float2*)(g_pairout + (size_t)pH * D_MODEL + fn0 + c) =
                        make_float2(w * d[i][j][2], w * d[i][j][3]);
                }
            }
        }
    }
}

// ---------------- combine: out[t] = pairout[2t] + pairout[2t+1] ----------------
__global__ void combine_kernel(float* __restrict__ out, int N) {
    int idx = blockIdx.x * blockDim.x + threadIdx.x;
    int total = N * (D_MODEL / 4);
    if (idx >= total) return;
    int t = idx / (D_MODEL / 4);
    int d4 = idx - t * (D_MODEL / 4);
    const float4* po = (const float4*)g_pairout;
    float4 a = po[(size_t)(2 * t) * (D_MODEL / 4) + d4];
    float4 b = po[(size_t)(2 * t + 1) * (D_MODEL / 4) + d4];
    ((float4*)out)[idx] = make_float4(a.x + b.x, a.y + b.y, a.z + b.z, a.w + b.w);
}

extern "C" void kernel_launch(void* const* d_in, const int* in_sizes, int n_in,
                              void* d_out, int out_size) {
    const float* x  = (const float*)d_in[0];
    const float* gw = (const float*)d_in[1];
    const float* W1 = (const float*)d_in[2];
    const float* W2 = (const float*)d_in[3];
    int N = in_sizes[0] / D_MODEL;

    // one-time host-side resource setup — SAME footprint as the passing R7 run
    // (3 streams, 5 events; the 8-stream variant tripped the memory tracker)
    static cudaStream_t s1, s2, s3;
    static cudaEvent_t ev_root, ev_s1, ev_s2, ev_s3, ev_build;
    static __half *w1t, *w2t;
    static bool init_done = false;
    if (!init_done) {
        cudaFuncSetAttribute(moe_gemm<0>, cudaFuncAttributeMaxDynamicSharedMemorySize, SMEM_TOT);
        cudaFuncSetAttribute(moe_gemm<1>, cudaFuncAttributeMaxDynamicSharedMemorySize, SMEM_TOT);
        cudaStreamCreateWithFlags(&s1, cudaStreamNonBlocking);
        cudaStreamCreateWithFlags(&s2, cudaStreamNonBlocking);
        cudaStreamCreateWithFlags(&s3, cudaStreamNonBlocking);
        cudaEventCreateWithFlags(&ev_root, cudaEventDisableTiming);
        cudaEventCreateWithFlags(&ev_s1, cudaEventDisableTiming);
        cudaEventCreateWithFlags(&ev_s2, cudaEventDisableTiming);
        cudaEventCreateWithFlags(&ev_s3, cudaEventDisableTiming);
        cudaEventCreateWithFlags(&ev_build, cudaEventDisableTiming);
        cudaGetSymbolAddress((void**)&w1t, g_W1t);
        cudaGetSymbolAddress((void**)&w2t, g_W2t);
        init_done = true;
    }

    dim3 blkT(32, 8);
    dim3 gt1(D_FF / 32, D_MODEL / 32, N_EXP);
    dim3 gt2(D_MODEL / 32, D_FF / 32, N_EXP);

    // fork prepass: s1 = convert_x, s2 = transpose W1, s3 = transpose W2
    cudaEventRecord(ev_root, 0);
    cudaStreamWaitEvent(s1, ev_root, 0);
    cudaStreamWaitEvent(s2, ev_root, 0);
    cudaStreamWaitEvent(s3, ev_root, 0);

    convert_x_kernel<<<(N * D_MODEL / 4 + 255) / 256, 256, 0, s1>>>(x, N * D_MODEL / 4);
    cudaEventRecord(ev_s1, s1);

    transpose_kernel<<<gt1, blkT, 0, s2>>>(W1, w1t, D_MODEL, D_FF);
    cudaEventRecord(ev_s2, s2);

    transpose_kernel<<<gt2, blkT, 0, s3>>>(W2, w2t, D_FF, D_MODEL);
    cudaEventRecord(ev_s3, s3);

    // main stream: gate + build
    gate_kernel<<<(N + 7) / 8, 256>>>(x, gw, N);
    build_kernel<<<1, 256>>>(N);
    cudaEventRecord(ev_build, 0);

    // 4 pipelines over 4 streams: {main: e0,e1} {s1: e2,e3} {s2: e4,e5} {s3: e6,e7}
    // In-stream order GEMM1_a, GEMM1_b, GEMM2_a, GEMM2_b gives per-expert deps for free.
    cudaStream_t pipes[4] = { (cudaStream_t)0, s1, s2, s3 };
    dim3 g1(D_FF / 128, 64, 1);
    dim3 g2(D_MODEL / 128, 64, 1);
    for (int q = 0; q < 4; q++) {
        cudaStream_t st = pipes[q];
        cudaStreamWaitEvent(st, ev_build, 0);
        cudaStreamWaitEvent(st, ev_s1, 0);
        cudaStreamWaitEvent(st, ev_s2, 0);
        moe_gemm<0><<<g1, 256, SMEM_TOT, st>>>(w1t, 2 * q);
        moe_gemm<0><<<g1, 256, SMEM_TOT, st>>>(w1t, 2 * q + 1);
        cudaStreamWaitEvent(st, ev_s3, 0);
        moe_gemm<1><<<g2, 256, SMEM_TOT, st>>>(w2t, 2 * q);
        moe_gemm<1><<<g2, 256, SMEM_TOT, st>>>(w2t, 2 * q + 1);
    }
    // join side pipes back to main (reuse side-stream events; re-record is capture-legal)
    cudaEventRecord(ev_s1, s1);
    cudaEventRecord(ev_s2, s2);
    cudaEventRecord(ev_s3, s3);
    cudaStreamWaitEvent(0, ev_s1, 0);
    cudaStreamWaitEvent(0, ev_s2, 0);
    cudaStreamWaitEvent(0, ev_s3, 0);

    combine_kernel<<<(N * (D_MODEL / 4) + 255) / 256, 256>>>((float*)d_out, N);
}

// round 11
// speedup vs baseline: 1.0435x; 1.0435x over previous
#include <cuda_runtime.h>
#include <cuda_fp16.h>
#include <math.h>
#include <stdint.h>

#define D_MODEL 1024
#define D_FF    4096
#define N_EXP   8
#define MAX_N   4096
#define MAX_PAIRS (2*MAX_N)
#define GRID_Y  10

// ---- scratch (static device globals; no runtime allocation) ----
__device__ __half g_xh[(size_t)MAX_N * D_MODEL];           // x in half
__device__ __half g_W1t[(size_t)N_EXP * D_FF * D_MODEL];   // W1^T: [e][n=4096][k=1024] half
__device__ __half g_W2t[(size_t)N_EXP * D_MODEL * D_FF];   // W2^T: [e][n=1024][k=4096] half
__device__ __half g_Hh[(size_t)MAX_PAIRS * D_FF];          // gelu(x@W1) per pair, half
__device__ float  g_pairout[(size_t)MAX_PAIRS * D_MODEL];  // per-pair weighted FFN out
__device__ int    g_pairlist[MAX_PAIRS];
__device__ int    g_cnt[N_EXP];
__device__ int    g_off[N_EXP];
__device__ int    g_tokexp[MAX_PAIRS];
__device__ float  g_tokw[MAX_PAIRS];

__device__ __forceinline__ float gelu_exact(float v) {
    return 0.5f * v * (1.0f + erff(v * 0.70710678118654752440f));
}
__device__ __forceinline__ uint32_t smem_u32(const void* p) {
    uint32_t a;
    asm("{ .reg .u64 t; cvta.to.shared.u64 t, %1; cvt.u32.u64 %0, t; }" : "=r"(a) : "l"(p));
    return a;
}
__device__ __forceinline__ void cp_async16(uint32_t dst, const void* src, int srcsize) {
    asm volatile("cp.async.ca.shared.global [%0], [%1], 16, %2;"
                 :: "r"(dst), "l"(src), "r"(srcsize) : "memory");
}
__device__ __forceinline__ void cp_commit() { asm volatile("cp.async.commit_group;" ::: "memory"); }
__device__ __forceinline__ void cp_wait1()  { asm volatile("cp.async.wait_group 1;" ::: "memory"); }

__device__ __forceinline__ void ldsm_x4(uint32_t* r, uint32_t addr) {
    asm volatile("ldmatrix.sync.aligned.m8n8.x4.shared.b16 {%0,%1,%2,%3}, [%4];"
                 : "=r"(r[0]), "=r"(r[1]), "=r"(r[2]), "=r"(r[3]) : "r"(addr));
}
__device__ __forceinline__ void mma_f16(float* d, const uint32_t* a, const uint32_t* b) {
    asm volatile(
        "mma.sync.aligned.m16n8k16.row.col.f32.f16.f16.f32 "
        "{%0,%1,%2,%3}, {%4,%5,%6,%7}, {%8,%9}, {%0,%1,%2,%3};"
        : "+f"(d[0]), "+f"(d[1]), "+f"(d[2]), "+f"(d[3])
        : "r"(a[0]), "r"(a[1]), "r"(a[2]), "r"(a[3]), "r"(b[0]), "r"(b[1]));
}

// ---------------- gate: logits -> softmax -> top2 (float4 loads) ----------------
__global__ void gate_kernel(const float* __restrict__ x,
                            const float* __restrict__ gw, int N) {
    __shared__ float s_gw[N_EXP][D_MODEL];
    int tid = threadIdx.x;
    for (int i = tid; i < N_EXP * D_MODEL / 4; i += blockDim.x) {
        float4 v = ((const float4*)gw)[i];
        int e = i >> 8, c = (i & 255) * 4;
        s_gw[e][c] = v.x; s_gw[e][c + 1] = v.y; s_gw[e][c + 2] = v.z; s_gw[e][c + 3] = v.w;
    }
    __syncthreads();

    int warp = tid >> 5, lane = tid & 31;
    int t = blockIdx.x * 8 + warp;
    if (t >= N) return;

    const float4* xr = (const float4*)(x + (size_t)t * D_MODEL);
    float acc[N_EXP];
#pragma unroll
    for (int e = 0; e < N_EXP; e++) acc[e] = 0.f;
#pragma unroll
    for (int it = 0; it < D_MODEL / 128; it++) {
        int d4 = it * 32 + lane;
        float4 xv = xr[d4];
        int d = d4 * 4;
#pragma unroll
        for (int e = 0; e < N_EXP; e++) {
            acc[e] += xv.x * s_gw[e][d] + xv.y * s_gw[e][d + 1]
                    + xv.z * s_gw[e][d + 2] + xv.w * s_gw[e][d + 3];
        }
    }
#pragma unroll
    for (int e = 0; e < N_EXP; e++) {
#pragma unroll
        for (int o = 16; o > 0; o >>= 1)
            acc[e] += __shfl_xor_sync(0xffffffffu, acc[e], o);
    }
    if (lane == 0) {
        float mx = acc[0];
#pragma unroll
        for (int e = 1; e < N_EXP; e++) mx = fmaxf(mx, acc[e]);
        float p[N_EXP]; float sum = 0.f;
#pragma unroll
        for (int e = 0; e < N_EXP; e++) { p[e] = expf(acc[e] - mx); sum += p[e]; }
        float inv = 1.0f / sum;
#pragma unroll
        for (int e = 0; e < N_EXP; e++) p[e] *= inv;
        int e0 = 0;
#pragma unroll
        for (int e = 1; e < N_EXP; e++) if (p[e] > p[e0]) e0 = e;
        int e1 = (e0 == 0) ? 1 : 0;
#pragma unroll
        for (int e = 0; e < N_EXP; e++) if (e != e0 && p[e] > p[e1]) e1 = e;
        g_tokexp[2 * t + 0] = e0; g_tokw[2 * t + 0] = p[e0];
        g_tokexp[2 * t + 1] = e1; g_tokw[2 * t + 1] = p[e1];
    }
}

// ------- deterministic per-expert compaction (stable counting sort) -------
__global__ void build_kernel(int N) {
    __shared__ int s_cnt[N_EXP];
    int tid = threadIdx.x, warp = tid >> 5, lane = tid & 31;
    int total = 2 * N;
    if (warp < N_EXP) {
        int c = 0;
        for (int i = lane; i < total; i += 32) c += (g_tokexp[i] == warp);
#pragma unroll
        for (int o = 16; o > 0; o >>= 1) c += __shfl_xor_sync(0xffffffffu, c, o);
        if (lane == 0) s_cnt[warp] = c;
    }
    __syncthreads();
    if (tid == 0) {
        int o = 0;
        for (int e = 0; e < N_EXP; e++) { g_off[e] = o; g_cnt[e] = s_cnt[e]; o += s_cnt[e]; }
    }
    __syncthreads();
    if (warp < N_EXP) {
        int run = g_off[warp];
        for (int base = 0; base < total; base += 32) {
            int i = base + lane;
            bool m = (i < total) && (g_tokexp[i] == warp);
            unsigned b = __ballot_sync(0xffffffffu, m);
            if (m) g_pairlist[run + __popc(b & ((1u << lane) - 1u))] = i;
            run += __popc(b);
        }
    }
}

// ---------------- prepass: convert & transpose ----------------
__global__ void convert_x_kernel(const float* __restrict__ x, int total4) {
    int i = blockIdx.x * blockDim.x + threadIdx.x;
    if (i >= total4) return;
    float4 v = ((const float4*)x)[i];
    __half2* o = (__half2*)g_xh;
    o[2 * i + 0] = __floats2half2_rn(v.x, v.y);
    o[2 * i + 1] = __floats2half2_rn(v.z, v.w);
}

// src [E][K][Nn] f32 -> dst [E][Nn][K] half  (tiled transpose, 8B coalesced writes)
__global__ void transpose_kernel(const float* __restrict__ src, __half* __restrict__ dst,
                                 int K, int Nn) {
    __shared__ float tile[32][33];
    int e = blockIdx.z;
    const float* s = src + (size_t)e * K * Nn;
    __half* d = dst + (size_t)e * K * Nn;
    int n0 = blockIdx.x * 32, k0 = blockIdx.y * 32;
    int tx = threadIdx.x, ty = threadIdx.y;  // 32 x 8
#pragma unroll
    for (int r = 0; r < 32; r += 8)
        tile[ty + r][tx] = s[(size_t)(k0 + ty + r) * Nn + n0 + tx];
    __syncthreads();
    int tid = ty * 32 + tx;
    int row = tid >> 3, ch = tid & 7;
    float v0 = tile[ch * 4 + 0][row];
    float v1 = tile[ch * 4 + 1][row];
    float v2 = tile[ch * 4 + 2][row];
    float v3 = tile[ch * 4 + 3][row];
    __half2 h0 = __floats2half2_rn(v0, v1);
    __half2 h1 = __floats2half2_rn(v2, v3);
    uint2 pack = make_uint2(*(uint32_t*)&h0, *(uint32_t*)&h1);
    *(uint2*)(d + (size_t)(n0 + row) * K + k0 + ch * 4) = pack;
}

// =================== fp16 mma GEMM: cp.async + ldmatrix, 2-stage ===================
// 128x128 tile, BK=64, 2 CTAs/SM. grid.y = GRID_Y with an in-kernel row-tile loop.
#define PITCH 144
#define A_STAGE_BYTES (128 * PITCH)
#define STAGE_BYTES   (2 * 128 * PITCH)
#define N_STAGES 2
#define SMEM_TOT (2048 + N_STAGES * STAGE_BYTES)

template <int MODE>
__global__ void __launch_bounds__(256, 2) moe_gemm(const __half* __restrict__ Wt) {
    constexpr int Ktot = (MODE == 0) ? D_MODEL : D_FF;
    constexpr int ITERS = Ktot / 64;

    int e = blockIdx.z;
    int cnt = g_cnt[e];
    int off = g_off[e];
    int fn0 = blockIdx.x * 128;
    const __half* We = Wt + (size_t)e * Ktot * ((MODE == 0) ? D_FF : D_MODEL);

    extern __shared__ __align__(128) char smem[];
    const __half** s_aptr = (const __half**)smem;
    int* s_pair = (int*)(smem + 1024);
    uint32_t sb = smem_u32(smem);
    uint32_t stage_base = sb + 2048;

    int tid = threadIdx.x, wid = tid >> 5, lane = tid & 31;
    int srow = tid >> 1;
    int halfsel = tid & 1;
    const __half* brow = We + (size_t)(fn0 + srow) * Ktot;

    int wm = wid >> 2, wn = wid & 3;  // warp tile: rows wm*64.., cols wn*32..
    int a_row_l = (lane & 15);
    int a_koff  = (lane >> 4) * 16;
    int b_grp   = lane >> 3;
    int b_row_l = (b_grp >> 1) * 8 + (lane & 7);
    int b_koff  = (b_grp & 1) * 16;
    int g = lane >> 2, t4 = lane & 3;

    for (int rt = blockIdx.y; rt * 128 < cnt; rt += GRID_Y) {
        int row0 = rt * 128;
        __syncthreads();   // previous tile's epilogue reads of s_pair complete
        if (tid < 128) {
            int r = row0 + tid;
            const __half* ip = nullptr; int p = -1;
            if (r < cnt) {
                p = g_pairlist[off + r];
                ip = (MODE == 0) ? (g_xh + (size_t)(p >> 1) * D_MODEL)
                                 : (g_Hh + (size_t)p * D_FF);
            }
            s_aptr[tid] = ip; s_pair[tid] = p;
        }
        __syncthreads();

        const __half* arow = s_aptr[srow];
        int a_sz = arow ? 16 : 0;
        if (!arow) arow = g_xh;

        auto stage = [&](int it) {
            if (it < ITERS) {
                uint32_t sA = stage_base + (it % N_STAGES) * STAGE_BYTES + srow * PITCH + halfsel * 64;
                uint32_t sB = sA + A_STAGE_BYTES;
                const char* ga = (const char*)(arow + it * 64) + halfsel * 64;
                const char* gb = (const char*)(brow + it * 64) + halfsel * 64;
#pragma unroll
                for (int c = 0; c < 4; c++) cp_async16(sA + c * 16, ga + c * 16, a_sz);
#pragma unroll
                for (int c = 0; c < 4; c++) cp_async16(sB + c * 16, gb + c * 16, 16);
            }
            cp_commit();
        };

        float d[4][4][4];
#pragma unroll
        for (int i = 0; i < 4; i++)
#pragma unroll
            for (int j = 0; j < 4; j++)
#pragma unroll
                for (int r = 0; r < 4; r++) d[i][j][r] = 0.f;

        stage(0);
        stage(1);

        for (int it = 0; it < ITERS; ++it) {
            cp_wait1();
            __syncthreads();
            uint32_t A = stage_base + (it % N_STAGES) * STAGE_BYTES;
            uint32_t B = A + A_STAGE_BYTES;
#pragma unroll
            for (int ks = 0; ks < 4; ks++) {
                uint32_t a[4][4], b[2][4];
#pragma unroll
                for (int i = 0; i < 4; i++)
                    ldsm_x4(a[i], A + (wm * 64 + i * 16 + a_row_l) * PITCH + ks * 32 + a_koff);
#pragma unroll
                for (int jj = 0; jj < 2; jj++)
                    ldsm_x4(b[jj], B + (wn * 32 + jj * 16 + b_row_l) * PITCH + ks * 32 + b_koff);
#pragma unroll
                for (int i = 0; i < 4; i++)
#pragma unroll
                    for (int j = 0; j < 4; j++)
                        mma_f16(d[i][j], a[i], &b[j >> 1][(j & 1) * 2]);
            }
            __syncthreads();
            stage(it + 2);
        }

        // ---- epilogue from accumulators (direct stores) ----
#pragma unroll
        for (int i = 0; i < 4; i++) {
            int rl = wm * 64 + i * 16 + g;
            int pL = s_pair[rl], pH = s_pair[rl + 8];
#pragma unroll
            for (int j = 0; j < 4; j++) {
                int c = wn * 32 + j * 8 + t4 * 2;
                if (MODE == 0) {
                    if (pL >= 0) {
                        __half2* o = (__half2*)(g_Hh + (size_t)pL * D_FF + fn0 + c);
                        *o = __floats2half2_rn(gelu_exact(d[i][j][0]), gelu_exact(d[i][j][1]));
                    }
                    if (pH >= 0) {
                        __half2* o = (__half2*)(g_Hh + (size_t)pH * D_FF + fn0 + c);
                        *o = __floats2half2_rn(gelu_exact(d[i][j][2]), gelu_exact(d[i][j][3]));
                    }
                } else {
                    if (pL >= 0) {
                        float w = g_tokw[pL];
                        *(float2*)(g_pairout + (size_t)pL * D_MODEL + fn0 + c) =
                            make_float2(w * d[i][j][0], w * d[i][j][1]);
                    }
                    if (pH >= 0) {
                        float w = g_tokw[pH];
                        *(float2*)(g_pairout + (size_t)pH * D_MODEL + fn0 + c) =
                            make_float2(w * d[i][j][2], w * d[i][j][3]);
                    }
                }
            }
        }
    }
}

// ---------------- combine: out[t] = pairout[2t] + pairout[2t+1] ----------------
__global__ void combine_kernel(float* __restrict__ out, int N) {
    int idx = blockIdx.x * blockDim.x + threadIdx.x;
    int total = N * (D_MODEL / 4);
    if (idx >= total) return;
    int t = idx / (D_MODEL / 4);
    int d4 = idx - t * (D_MODEL / 4);
    const float4* po = (const float4*)g_pairout;
    float4 a = po[(size_t)(2 * t) * (D_MODEL / 4) + d4];
    float4 b = po[(size_t)(2 * t + 1) * (D_MODEL / 4) + d4];
    ((float4*)out)[idx] = make_float4(a.x + b.x, a.y + b.y, a.z + b.z, a.w + b.w);
}

extern "C" void kernel_launch(void* const* d_in, const int* in_sizes, int n_in,
                              void* d_out, int out_size) {
    const float* x  = (const float*)d_in[0];
    const float* gw = (const float*)d_in[1];
    const float* W1 = (const float*)d_in[2];
    const float* W2 = (const float*)d_in[3];
    int N = in_sizes[0] / D_MODEL;

    // one-time host-side resource setup (same footprint as the passing R7 run)
    static cudaStream_t s1, s2, s3;
    static cudaEvent_t ev_root, ev_s1, ev_s2, ev_s3;
    static __half *w1t, *w2t;
    static bool init_done = false;
    if (!init_done) {
        cudaFuncSetAttribute(moe_gemm<0>, cudaFuncAttributeMaxDynamicSharedMemorySize, SMEM_TOT);
        cudaFuncSetAttribute(moe_gemm<1>, cudaFuncAttributeMaxDynamicSharedMemorySize, SMEM_TOT);
        cudaStreamCreateWithFlags(&s1, cudaStreamNonBlocking);
        cudaStreamCreateWithFlags(&s2, cudaStreamNonBlocking);
        cudaStreamCreateWithFlags(&s3, cudaStreamNonBlocking);
        cudaEventCreateWithFlags(&ev_root, cudaEventDisableTiming);
        cudaEventCreateWithFlags(&ev_s1, cudaEventDisableTiming);
        cudaEventCreateWithFlags(&ev_s2, cudaEventDisableTiming);
        cudaEventCreateWithFlags(&ev_s3, cudaEventDisableTiming);
        cudaGetSymbolAddress((void**)&w1t, g_W1t);
        cudaGetSymbolAddress((void**)&w2t, g_W2t);
        init_done = true;
    }

    dim3 blkT(32, 8);
    dim3 gt1(D_FF / 32, D_MODEL / 32, N_EXP);
    dim3 gt2(D_MODEL / 32, D_FF / 32, N_EXP);

    // fork: s1 = convert_x, s2 = transpose W1, s3 = transpose W2
    cudaEventRecord(ev_root, 0);
    cudaStreamWaitEvent(s1, ev_root, 0);
    cudaStreamWaitEvent(s2, ev_root, 0);
    cudaStreamWaitEvent(s3, ev_root, 0);

    convert_x_kernel<<<(N * D_MODEL / 4 + 255) / 256, 256, 0, s1>>>(x, N * D_MODEL / 4);
    cudaEventRecord(ev_s1, s1);

    transpose_kernel<<<gt1, blkT, 0, s2>>>(W1, w1t, D_MODEL, D_FF);
    cudaEventRecord(ev_s2, s2);

    transpose_kernel<<<gt2, blkT, 0, s3>>>(W2, w2t, D_FF, D_MODEL);
    cudaEventRecord(ev_s3, s3);

    // main stream: gate + build (depend only on x, gw)
    gate_kernel<<<(N + 7) / 8, 256>>>(x, gw, N);
    build_kernel<<<1, 256>>>(N);

    // GEMM1 needs: build (main), convert_x (s1), W1t (s2). W2 transpose (s3) keeps running.
    cudaStreamWaitEvent(0, ev_s1, 0);
    cudaStreamWaitEvent(0, ev_s2, 0);
    dim3 g1(D_FF / 128, GRID_Y, N_EXP);
    moe_gemm<0><<<g1, 256, SMEM_TOT>>>(w1t);

    // GEMM2 additionally needs W2t (s3) — its transpose overlapped GEMM1.
    cudaStreamWaitEvent(0, ev_s3, 0);
    dim3 g2(D_MODEL / 128, GRID_Y, N_EXP);
    moe_gemm<1><<<g2, 256, SMEM_TOT>>>(w2t);

    combine_kernel<<<(N * (D_MODEL / 4) + 255) / 256, 256>>>((float*)d_out, N);
}